// round 1
// baseline (speedup 1.0000x reference)
#include <cuda_runtime.h>

#define NN 100000
#define EE 1600000
#define HH 128

// ---------------- scratch (static device globals; no runtime alloc) ----------------
__device__ int   DEG[NN];
__device__ int   CURSOR[NN];
__device__ int   ROWPTR[NN + 1];
__device__ int   COLIDX[EE];
__device__ float DINV[NN];
__device__ float BUF_G[(size_t)NN * HH];   // scaled pre-aggregation features g = h * dinv
__device__ float BUF_Z[(size_t)NN * HH];   // post-aggregation activations z
__device__ int   BLKSUM[256];

// ---------------- CSR build ----------------
__global__ void k_zero() {
    int i = blockIdx.x * blockDim.x + threadIdx.x;
    if (i < NN) { DEG[i] = 0; CURSOR[i] = 0; }
}

__global__ void k_hist(const int* __restrict__ dst) {
    int e = blockIdx.x * blockDim.x + threadIdx.x;
    if (e < EE) atomicAdd(&DEG[dst[e]], 1);
}

__global__ void k_dinv() {
    int i = blockIdx.x * blockDim.x + threadIdx.x;
    if (i < NN) DINV[i] = rsqrtf((float)(DEG[i] + 1));  // +1 self-loop
}

__global__ void k_scan1() {
    __shared__ int s[512];
    int i = blockIdx.x * 512 + threadIdx.x;
    int v = (i < NN) ? DEG[i] : 0;
    s[threadIdx.x] = v;
    __syncthreads();
    for (int off = 1; off < 512; off <<= 1) {
        int t = 0;
        if (threadIdx.x >= off) t = s[threadIdx.x - off];
        __syncthreads();
        if (threadIdx.x >= off) s[threadIdx.x] += t;
        __syncthreads();
    }
    if (i < NN) ROWPTR[i] = s[threadIdx.x] - v;     // exclusive
    if (threadIdx.x == 511) BLKSUM[blockIdx.x] = s[511];
}

__global__ void k_scan2() {
    __shared__ int s[256];
    const int NB = (NN + 511) / 512;                 // 196
    int v = (threadIdx.x < NB) ? BLKSUM[threadIdx.x] : 0;
    s[threadIdx.x] = v;
    __syncthreads();
    for (int off = 1; off < 256; off <<= 1) {
        int t = 0;
        if (threadIdx.x >= off) t = s[threadIdx.x - off];
        __syncthreads();
        if (threadIdx.x >= off) s[threadIdx.x] += t;
        __syncthreads();
    }
    BLKSUM[threadIdx.x] = s[threadIdx.x] - v;        // exclusive block offsets
}

__global__ void k_scan3() {
    int i = blockIdx.x * blockDim.x + threadIdx.x;
    if (i < NN) ROWPTR[i] += BLKSUM[i >> 9];
    if (i == 0) ROWPTR[NN] = EE;
}

__global__ void k_scatter(const int* __restrict__ src, const int* __restrict__ dst) {
    int e = blockIdx.x * blockDim.x + threadIdx.x;
    if (e >= EE) return;
    int d = dst[e];
    int p = ROWPTR[d] + atomicAdd(&CURSOR[d], 1);
    COLIDX[p] = src[e];
}

// ---------------- layer 1: g1[i,c] = x[i]*dinv[i]*W1[c]  (fan_in = 1) ----------------
__global__ void k_layer1(const float* __restrict__ x, const float4* __restrict__ W1) {
    int i = blockIdx.x * blockDim.x + threadIdx.x;
    if (i >= NN * 32) return;
    int node = i >> 5, lane = i & 31;
    float s = x[node] * DINV[node];
    float4 w = W1[lane];
    reinterpret_cast<float4*>(BUF_G)[i] = make_float4(s * w.x, s * w.y, s * w.z, s * w.w);
}

// ---------------- aggregation (pull, CSR): z[i] = act(dinv[i]*(g[i] + sum_nbr g[src]) + b) ----
template <bool RELU>
__global__ void k_agg(const float4* __restrict__ bias) {
    int node = (blockIdx.x * blockDim.x + threadIdx.x) >> 5;   // 1 warp per node
    if (node >= NN) return;
    int lane = threadIdx.x & 31;
    const float4* g = reinterpret_cast<const float4*>(BUF_G);
    float4 acc = g[node * 32 + lane];                           // self-loop term
    int beg = ROWPTR[node], end = ROWPTR[node + 1];
    int e = beg;
    for (; e + 4 <= end; e += 4) {
        int s0 = COLIDX[e], s1 = COLIDX[e + 1], s2 = COLIDX[e + 2], s3 = COLIDX[e + 3];
        float4 a0 = g[s0 * 32 + lane], a1 = g[s1 * 32 + lane];
        float4 a2 = g[s2 * 32 + lane], a3 = g[s3 * 32 + lane];
        acc.x += (a0.x + a1.x) + (a2.x + a3.x);
        acc.y += (a0.y + a1.y) + (a2.y + a3.y);
        acc.z += (a0.z + a1.z) + (a2.z + a3.z);
        acc.w += (a0.w + a1.w) + (a2.w + a3.w);
    }
    for (; e < end; ++e) {
        float4 a = g[COLIDX[e] * 32 + lane];
        acc.x += a.x; acc.y += a.y; acc.z += a.z; acc.w += a.w;
    }
    float di = DINV[node];
    float4 b = bias[lane];
    float4 r = make_float4(fmaf(acc.x, di, b.x), fmaf(acc.y, di, b.y),
                           fmaf(acc.z, di, b.z), fmaf(acc.w, di, b.w));
    if (RELU) {
        r.x = fmaxf(r.x, 0.f); r.y = fmaxf(r.y, 0.f);
        r.z = fmaxf(r.z, 0.f); r.w = fmaxf(r.w, 0.f);
    }
    reinterpret_cast<float4*>(BUF_Z)[node * 32 + lane] = r;
}

// ---------------- SGEMM: C = BUF_Z @ W  (K=128), epilogue: *dinv (SCALE) or +bias (BIAS) ----
template <int COUT, bool SCALE, bool BIAS>
__global__ void __launch_bounds__(16 * (COUT / 8))
k_gemm(const float* __restrict__ W, const float* __restrict__ bias, float* __restrict__ outp) {
    constexpr int BM = 64, BK = 64, TM = 4, TN = 8;
    constexpr int TX = COUT / TN;          // 16 (COUT=128) or 8 (COUT=64)
    constexpr int NT = TX * 16;
    __shared__ __align__(16) float As[BM][BK];
    __shared__ __align__(16) float Ws[BK][COUT];

    int tx = threadIdx.x, ty = threadIdx.y;
    int tid = ty * TX + tx;
    int row0 = blockIdx.x * BM;
    float acc[TM][TN] = {};
    const float4* A4 = reinterpret_cast<const float4*>(BUF_Z);

    for (int kb = 0; kb < HH; kb += BK) {
        for (int t = tid; t < BM * BK / 4; t += NT) {
            int r = t >> 4, kk = t & 15;          // BK/4 = 16
            int grow = row0 + r;
            float4 v = make_float4(0.f, 0.f, 0.f, 0.f);
            if (grow < NN) v = A4[grow * 32 + (kb >> 2) + kk];
            reinterpret_cast<float4*>(&As[r][0])[kk] = v;
        }
        for (int t = tid; t < BK * COUT / 4; t += NT) {
            int r = t / (COUT / 4), cc = t % (COUT / 4);
            reinterpret_cast<float4*>(&Ws[r][0])[cc] =
                reinterpret_cast<const float4*>(W)[(kb + r) * (COUT / 4) + cc];
        }
        __syncthreads();
        #pragma unroll 8
        for (int k = 0; k < BK; k++) {
            float a[TM];
            #pragma unroll
            for (int i = 0; i < TM; i++) a[i] = As[ty * TM + i][k];
            float4 b0 = reinterpret_cast<float4*>(&Ws[k][0])[tx * 2];
            float4 b1 = reinterpret_cast<float4*>(&Ws[k][0])[tx * 2 + 1];
            float b[TN] = {b0.x, b0.y, b0.z, b0.w, b1.x, b1.y, b1.z, b1.w};
            #pragma unroll
            for (int i = 0; i < TM; i++)
                #pragma unroll
                for (int j = 0; j < TN; j++)
                    acc[i][j] = fmaf(a[i], b[j], acc[i][j]);
        }
        __syncthreads();
    }

    float* Cm = SCALE ? BUF_G : outp;
    #pragma unroll
    for (int i = 0; i < TM; i++) {
        int r = row0 + ty * TM + i;
        if (r >= NN) continue;
        float sc = SCALE ? DINV[r] : 1.0f;
        float4 v0 = make_float4(acc[i][0], acc[i][1], acc[i][2], acc[i][3]);
        float4 v1 = make_float4(acc[i][4], acc[i][5], acc[i][6], acc[i][7]);
        if (SCALE) {
            v0.x *= sc; v0.y *= sc; v0.z *= sc; v0.w *= sc;
            v1.x *= sc; v1.y *= sc; v1.z *= sc; v1.w *= sc;
        }
        if (BIAS) {
            float4 bb0 = reinterpret_cast<const float4*>(bias)[tx * 2];
            float4 bb1 = reinterpret_cast<const float4*>(bias)[tx * 2 + 1];
            v0.x += bb0.x; v0.y += bb0.y; v0.z += bb0.z; v0.w += bb0.w;
            v1.x += bb1.x; v1.y += bb1.y; v1.z += bb1.z; v1.w += bb1.w;
        }
        reinterpret_cast<float4*>(Cm)[r * (COUT / 4) + tx * 2]     = v0;
        reinterpret_cast<float4*>(Cm)[r * (COUT / 4) + tx * 2 + 1] = v1;
    }
}

// ---------------- launch ----------------
extern "C" void kernel_launch(void* const* d_in, const int* in_sizes, int n_in,
                              void* d_out, int out_size) {
    const float* x  = (const float*)d_in[0];
    const int*   ei = (const int*)d_in[1];
    const int*   src = ei;
    const int*   dst = ei + EE;
    const float* W1 = (const float*)d_in[2];
    const float* b1 = (const float*)d_in[3];
    const float* W2 = (const float*)d_in[4];
    const float* b2 = (const float*)d_in[5];
    const float* W3 = (const float*)d_in[6];
    const float* b3 = (const float*)d_in[7];
    const float* Wo = (const float*)d_in[8];
    const float* bo = (const float*)d_in[9];
    float* out = (float*)d_out;

    // CSR build (per launch — no caching allowed)
    k_zero   <<<(NN + 255) / 256, 256>>>();
    k_hist   <<<(EE + 255) / 256, 256>>>(dst);
    k_dinv   <<<(NN + 255) / 256, 256>>>();
    k_scan1  <<<(NN + 511) / 512, 512>>>();
    k_scan2  <<<1, 256>>>();
    k_scan3  <<<(NN + 255) / 256, 256>>>();
    k_scatter<<<(EE + 255) / 256, 256>>>(src, dst);

    // layer 1 (fan_in=1 outer product), then agg
    k_layer1<<<(NN * 32 + 255) / 256, 256>>>(x, (const float4*)W1);
    k_agg<true><<<(NN + 7) / 8, 256>>>((const float4*)b1);

    // layer 2
    k_gemm<128, true, false><<<(NN + 63) / 64, dim3(16, 16)>>>(W2, nullptr, nullptr);
    k_agg<true><<<(NN + 7) / 8, 256>>>((const float4*)b2);

    // layer 3 (no relu)
    k_gemm<128, true, false><<<(NN + 63) / 64, dim3(16, 16)>>>(W3, nullptr, nullptr);
    k_agg<false><<<(NN + 7) / 8, 256>>>((const float4*)b3);

    // linear head -> d_out
    k_gemm<64, false, true><<<(NN + 63) / 64, dim3(8, 16)>>>(Wo, bo, out);
}

// round 2
// speedup vs baseline: 1.0690x; 1.0690x over previous
#include <cuda_runtime.h>

#define NN 100000
#define EE 1600000
#define HH 128

// ---------------- scratch (static device globals; no runtime alloc) ----------------
__device__ int   DEG[NN];
__device__ int   CURSOR[NN];
__device__ int   ROWPTR[NN + 1];
__device__ int   COLIDX[EE];
__device__ float DINV[NN];
__device__ float XD[NN];                   // x[i]*dinv[i]
__device__ float TSUM[NN];                 // layer-1 scalar aggregate (incl. dinv[i])
__device__ float BUF_G[(size_t)NN * HH];   // scaled pre-aggregation features g = h * dinv
__device__ float BUF_Z[(size_t)NN * HH];   // post-aggregation activations z
__device__ int   BLKSUM[256];

// ---------------- packed f32x2 helpers ----------------
__device__ __forceinline__ unsigned long long ffma2(unsigned long long a,
                                                    unsigned long long b,
                                                    unsigned long long c) {
    unsigned long long d;
    asm("fma.rn.f32x2 %0, %1, %2, %3;" : "=l"(d) : "l"(a), "l"(b), "l"(c));
    return d;
}
__device__ __forceinline__ unsigned long long pack2(float v) {
    unsigned long long d;
    asm("mov.b64 %0, {%1, %1};" : "=l"(d) : "f"(v), "f"(v));
    return d;
}
__device__ __forceinline__ float2 unpack2(unsigned long long p) {
    float2 u;
    asm("mov.b64 {%0, %1}, %2;" : "=f"(u.x), "=f"(u.y) : "l"(p));
    return u;
}

// ---------------- CSR build ----------------
__global__ void k_zero() {
    int i = blockIdx.x * blockDim.x + threadIdx.x;
    if (i < NN) { DEG[i] = 0; CURSOR[i] = 0; }
}

__global__ void k_hist(const int* __restrict__ dst) {
    int e = blockIdx.x * blockDim.x + threadIdx.x;
    if (e < EE) atomicAdd(&DEG[dst[e]], 1);
}

// scan over DEG (block-local) + compute DINV and XD in the same pass
__global__ void k_scan1(const float* __restrict__ x) {
    __shared__ int s[512];
    int i = blockIdx.x * 512 + threadIdx.x;
    int v = (i < NN) ? DEG[i] : 0;
    s[threadIdx.x] = v;
    __syncthreads();
    for (int off = 1; off < 512; off <<= 1) {
        int t = 0;
        if (threadIdx.x >= off) t = s[threadIdx.x - off];
        __syncthreads();
        if (threadIdx.x >= off) s[threadIdx.x] += t;
        __syncthreads();
    }
    if (i < NN) {
        ROWPTR[i] = s[threadIdx.x] - v;     // exclusive
        float di = rsqrtf((float)(v + 1));  // +1 self-loop
        DINV[i] = di;
        XD[i] = x[i] * di;
    }
    if (threadIdx.x == 511) BLKSUM[blockIdx.x] = s[511];
}

__global__ void k_scan2() {
    __shared__ int s[256];
    const int NB = (NN + 511) / 512;
    int v = (threadIdx.x < NB) ? BLKSUM[threadIdx.x] : 0;
    s[threadIdx.x] = v;
    __syncthreads();
    for (int off = 1; off < 256; off <<= 1) {
        int t = 0;
        if (threadIdx.x >= off) t = s[threadIdx.x - off];
        __syncthreads();
        if (threadIdx.x >= off) s[threadIdx.x] += t;
        __syncthreads();
    }
    BLKSUM[threadIdx.x] = s[threadIdx.x] - v;
}

__global__ void k_scan3() {
    int i = blockIdx.x * blockDim.x + threadIdx.x;
    if (i < NN) ROWPTR[i] += BLKSUM[i >> 9];
    if (i == 0) ROWPTR[NN] = EE;
}

__global__ void k_scatter(const int* __restrict__ src, const int* __restrict__ dst) {
    int e = blockIdx.x * blockDim.x + threadIdx.x;
    if (e >= EE) return;
    int d = dst[e];
    int p = ROWPTR[d] + atomicAdd(&CURSOR[d], 1);
    COLIDX[p] = src[e];
}

// ---------------- layer-1 scalar aggregation: t[i] = dinv[i]*(xd[i] + sum_nbr xd[s]) ----
__global__ void k_scalar_agg() {
    int i = blockIdx.x * blockDim.x + threadIdx.x;
    if (i >= NN) return;
    float t = XD[i];
    int e = ROWPTR[i], end = ROWPTR[i + 1];
    for (; e + 4 <= end; e += 4) {
        float a0 = XD[COLIDX[e]],     a1 = XD[COLIDX[e + 1]];
        float a2 = XD[COLIDX[e + 2]], a3 = XD[COLIDX[e + 3]];
        t += (a0 + a1) + (a2 + a3);
    }
    for (; e < end; ++e) t += XD[COLIDX[e]];
    TSUM[i] = t * DINV[i];
}

// ---------------- layer-1 expand: z1[i,c] = relu(t[i]*W1[c] + b1[c]) -> BUF_Z ----------
__global__ void k_expand(const float4* __restrict__ W1, const float4* __restrict__ b1) {
    int i = blockIdx.x * blockDim.x + threadIdx.x;
    if (i >= NN * 32) return;
    int node = i >> 5, lane = i & 31;
    float s = TSUM[node];
    float4 w = W1[lane], b = b1[lane];
    float4 r = make_float4(fmaxf(fmaf(s, w.x, b.x), 0.f), fmaxf(fmaf(s, w.y, b.y), 0.f),
                           fmaxf(fmaf(s, w.z, b.z), 0.f), fmaxf(fmaf(s, w.w, b.w), 0.f));
    reinterpret_cast<float4*>(BUF_Z)[i] = r;
}

// ---------------- aggregation (pull, CSR): z[i] = act(dinv[i]*(g[i] + sum_nbr g[s]) + b) ----
template <bool RELU>
__global__ void k_agg(const float4* __restrict__ bias) {
    int node = (blockIdx.x * blockDim.x + threadIdx.x) >> 5;   // 1 warp per node
    if (node >= NN) return;
    int lane = threadIdx.x & 31;
    const float4* g = reinterpret_cast<const float4*>(BUF_G);
    float4 acc = g[node * 32 + lane];                           // self-loop term
    int beg = ROWPTR[node], end = ROWPTR[node + 1];
    int e = beg;
    for (; e + 4 <= end; e += 4) {
        int s0 = COLIDX[e], s1 = COLIDX[e + 1], s2 = COLIDX[e + 2], s3 = COLIDX[e + 3];
        float4 a0 = g[s0 * 32 + lane], a1 = g[s1 * 32 + lane];
        float4 a2 = g[s2 * 32 + lane], a3 = g[s3 * 32 + lane];
        acc.x += (a0.x + a1.x) + (a2.x + a3.x);
        acc.y += (a0.y + a1.y) + (a2.y + a3.y);
        acc.z += (a0.z + a1.z) + (a2.z + a3.z);
        acc.w += (a0.w + a1.w) + (a2.w + a3.w);
    }
    for (; e < end; ++e) {
        float4 a = g[COLIDX[e] * 32 + lane];
        acc.x += a.x; acc.y += a.y; acc.z += a.z; acc.w += a.w;
    }
    float di = DINV[node];
    float4 b = bias[lane];
    float4 r = make_float4(fmaf(acc.x, di, b.x), fmaf(acc.y, di, b.y),
                           fmaf(acc.z, di, b.z), fmaf(acc.w, di, b.w));
    if (RELU) {
        r.x = fmaxf(r.x, 0.f); r.y = fmaxf(r.y, 0.f);
        r.z = fmaxf(r.z, 0.f); r.w = fmaxf(r.w, 0.f);
    }
    reinterpret_cast<float4*>(BUF_Z)[node * 32 + lane] = r;
}

// ---------------- SGEMM (packed f32x2): C = BUF_Z @ W, epilogue *dinv or +bias ----------
template <int COUT, bool SCALE, bool BIAS>
__global__ void __launch_bounds__(16 * (COUT / 8))
k_gemm(const float* __restrict__ W, const float* __restrict__ bias, float* __restrict__ outp) {
    constexpr int BM = 64, BK = 64, TM = 4, TN = 8;
    constexpr int TX = COUT / TN;          // 16 (COUT=128) or 8 (COUT=64)
    constexpr int NT = TX * 16;
    constexpr int WPAD = COUT + 8;         // row pad against LDS bank conflicts
    __shared__ __align__(16) float As[BM][BK];
    __shared__ __align__(16) float Ws[BK][WPAD];

    int tx = threadIdx.x, ty = threadIdx.y;
    int tid = ty * TX + tx;
    int row0 = blockIdx.x * BM;
    unsigned long long acc[TM][TN / 2] = {};   // 0 bits == {0.f, 0.f}
    const float4* A4 = reinterpret_cast<const float4*>(BUF_Z);

    for (int kb = 0; kb < HH; kb += BK) {
        for (int t = tid; t < BM * BK / 4; t += NT) {
            int r = t >> 4, kk = t & 15;          // BK/4 = 16
            int grow = row0 + r;
            float4 v = make_float4(0.f, 0.f, 0.f, 0.f);
            if (grow < NN) v = A4[grow * 32 + (kb >> 2) + kk];
            reinterpret_cast<float4*>(&As[r][0])[kk] = v;
        }
        for (int t = tid; t < BK * COUT / 4; t += NT) {
            int r = t / (COUT / 4), cc = t % (COUT / 4);
            reinterpret_cast<float4*>(&Ws[r][0])[cc] =
                reinterpret_cast<const float4*>(W)[(kb + r) * (COUT / 4) + cc];
        }
        __syncthreads();
        #pragma unroll 8
        for (int k = 0; k < BK; k++) {
            const unsigned long long* wr =
                reinterpret_cast<const unsigned long long*>(&Ws[k][0]);
            unsigned long long bp0 = wr[tx * 4 + 0];
            unsigned long long bp1 = wr[tx * 4 + 1];
            unsigned long long bp2 = wr[tx * 4 + 2];
            unsigned long long bp3 = wr[tx * 4 + 3];
            #pragma unroll
            for (int i = 0; i < TM; i++) {
                unsigned long long pa = pack2(As[ty * TM + i][k]);
                acc[i][0] = ffma2(pa, bp0, acc[i][0]);
                acc[i][1] = ffma2(pa, bp1, acc[i][1]);
                acc[i][2] = ffma2(pa, bp2, acc[i][2]);
                acc[i][3] = ffma2(pa, bp3, acc[i][3]);
            }
        }
        __syncthreads();
    }

    float* Cm = SCALE ? BUF_G : outp;
    #pragma unroll
    for (int i = 0; i < TM; i++) {
        int r = row0 + ty * TM + i;
        if (r >= NN) continue;
        float sc = SCALE ? DINV[r] : 1.0f;
        float2 p0 = unpack2(acc[i][0]), p1 = unpack2(acc[i][1]);
        float2 p2 = unpack2(acc[i][2]), p3 = unpack2(acc[i][3]);
        float4 v0 = make_float4(p0.x, p0.y, p1.x, p1.y);
        float4 v1 = make_float4(p2.x, p2.y, p3.x, p3.y);
        if (SCALE) {
            v0.x *= sc; v0.y *= sc; v0.z *= sc; v0.w *= sc;
            v1.x *= sc; v1.y *= sc; v1.z *= sc; v1.w *= sc;
        }
        if (BIAS) {
            float4 bb0 = reinterpret_cast<const float4*>(bias)[tx * 2];
            float4 bb1 = reinterpret_cast<const float4*>(bias)[tx * 2 + 1];
            v0.x += bb0.x; v0.y += bb0.y; v0.z += bb0.z; v0.w += bb0.w;
            v1.x += bb1.x; v1.y += bb1.y; v1.z += bb1.z; v1.w += bb1.w;
        }
        reinterpret_cast<float4*>(Cm)[r * (COUT / 4) + tx * 2]     = v0;
        reinterpret_cast<float4*>(Cm)[r * (COUT / 4) + tx * 2 + 1] = v1;
    }
}

// ---------------- launch ----------------
extern "C" void kernel_launch(void* const* d_in, const int* in_sizes, int n_in,
                              void* d_out, int out_size) {
    const float* x  = (const float*)d_in[0];
    const int*   ei = (const int*)d_in[1];
    const int*   src = ei;
    const int*   dst = ei + EE;
    const float* W1 = (const float*)d_in[2];
    const float* b1 = (const float*)d_in[3];
    const float* W2 = (const float*)d_in[4];
    const float* b2 = (const float*)d_in[5];
    const float* W3 = (const float*)d_in[6];
    const float* b3 = (const float*)d_in[7];
    const float* Wo = (const float*)d_in[8];
    const float* bo = (const float*)d_in[9];
    float* out = (float*)d_out;

    // CSR build (per launch — no caching allowed)
    k_zero   <<<(NN + 255) / 256, 256>>>();
    k_hist   <<<(EE + 255) / 256, 256>>>(dst);
    k_scan1  <<<(NN + 511) / 512, 512>>>(x);
    k_scan2  <<<1, 256>>>();
    k_scan3  <<<(NN + 255) / 256, 256>>>();
    k_scatter<<<(EE + 255) / 256, 256>>>(src, dst);

    // layer 1 (rank-1 factorized: scalar aggregate + outer-product expand)
    k_scalar_agg<<<(NN + 255) / 256, 256>>>();
    k_expand<<<(NN * 32 + 255) / 256, 256>>>((const float4*)W1, (const float4*)b1);

    // layer 2
    k_gemm<128, true, false><<<(NN + 63) / 64, dim3(16, 16)>>>(W2, nullptr, nullptr);
    k_agg<true><<<(NN + 7) / 8, 256>>>((const float4*)b2);

    // layer 3 (no relu)
    k_gemm<128, true, false><<<(NN + 63) / 64, dim3(16, 16)>>>(W3, nullptr, nullptr);
    k_agg<false><<<(NN + 7) / 8, 256>>>((const float4*)b3);

    // linear head -> d_out
    k_gemm<64, false, true><<<(NN + 63) / 64, dim3(8, 16)>>>(Wo, bo, out);
}

// round 5
// speedup vs baseline: 1.2701x; 1.1880x over previous
#include <cuda_runtime.h>
#include <cstdint>

#define NN 100000
#define EE 1600000
#define HH 128

// ---------------- scratch (static device globals; no runtime alloc) ----------------
__device__ int   DEG[NN];
__device__ int   CURSOR[NN];
__device__ int   ROWPTR[NN + 1];
__device__ int   COLIDX[EE];
__device__ float DINV[NN];
__device__ float XD[NN];
__device__ float TSUM[NN];
__device__ float BUF_G[(size_t)NN * HH];
__device__ float BUF_Z[(size_t)NN * HH];
__device__ int   BLKSUM[256];

// ---------------- helpers ----------------
__device__ __forceinline__ unsigned long long ffma2(unsigned long long a,
                                                    unsigned long long b,
                                                    unsigned long long c) {
    unsigned long long d;
    asm("fma.rn.f32x2 %0, %1, %2, %3;" : "=l"(d) : "l"(a), "l"(b), "l"(c));
    return d;
}
__device__ __forceinline__ unsigned long long pack2(float v) {
    unsigned long long d;
    asm("mov.b64 %0, {%1, %1};" : "=l"(d) : "f"(v), "f"(v));
    return d;
}
__device__ __forceinline__ float2 unpack2(unsigned long long p) {
    float2 u;
    asm("mov.b64 {%0, %1}, %2;" : "=f"(u.x), "=f"(u.y) : "l"(p));
    return u;
}
__device__ __forceinline__ float tf32r(float x) {   // round-to-nearest tf32 (zero-mean err)
    float r;
    asm("cvt.rna.tf32.f32 %0, %1;" : "=f"(r) : "f"(x));
    return r;
}

// ---------------- CSR build ----------------
__global__ void k_zero() {
    int i = blockIdx.x * blockDim.x + threadIdx.x;
    if (i < NN) { DEG[i] = 0; CURSOR[i] = 0; }
}
__global__ void k_hist(const int* __restrict__ dst) {
    int e = blockIdx.x * blockDim.x + threadIdx.x;
    if (e < EE) atomicAdd(&DEG[dst[e]], 1);
}
__global__ void k_scan1(const float* __restrict__ x) {
    __shared__ int s[512];
    int i = blockIdx.x * 512 + threadIdx.x;
    int v = (i < NN) ? DEG[i] : 0;
    s[threadIdx.x] = v;
    __syncthreads();
    for (int off = 1; off < 512; off <<= 1) {
        int t = 0;
        if (threadIdx.x >= off) t = s[threadIdx.x - off];
        __syncthreads();
        if (threadIdx.x >= off) s[threadIdx.x] += t;
        __syncthreads();
    }
    if (i < NN) {
        ROWPTR[i] = s[threadIdx.x] - v;
        float di = rsqrtf((float)(v + 1));
        DINV[i] = di;
        XD[i] = x[i] * di;
    }
    if (threadIdx.x == 511) BLKSUM[blockIdx.x] = s[511];
}
__global__ void k_scan2() {
    __shared__ int s[256];
    const int NB = (NN + 511) / 512;
    int v = (threadIdx.x < NB) ? BLKSUM[threadIdx.x] : 0;
    s[threadIdx.x] = v;
    __syncthreads();
    for (int off = 1; off < 256; off <<= 1) {
        int t = 0;
        if (threadIdx.x >= off) t = s[threadIdx.x - off];
        __syncthreads();
        if (threadIdx.x >= off) s[threadIdx.x] += t;
        __syncthreads();
    }
    BLKSUM[threadIdx.x] = s[threadIdx.x] - v;
}
__global__ void k_scan3() {
    int i = blockIdx.x * blockDim.x + threadIdx.x;
    if (i < NN) ROWPTR[i] += BLKSUM[i >> 9];
    if (i == 0) ROWPTR[NN] = EE;
}
__global__ void k_scatter(const int* __restrict__ src, const int* __restrict__ dst) {
    int e = blockIdx.x * blockDim.x + threadIdx.x;
    if (e >= EE) return;
    int d = dst[e];
    int p = ROWPTR[d] + atomicAdd(&CURSOR[d], 1);
    COLIDX[p] = src[e];
}

// ---------------- layer-1 rank-1 path ----------------
__global__ void k_scalar_agg() {
    int i = blockIdx.x * blockDim.x + threadIdx.x;
    if (i >= NN) return;
    float t = XD[i];
    int e = ROWPTR[i], end = ROWPTR[i + 1];
    for (; e + 4 <= end; e += 4) {
        float a0 = XD[COLIDX[e]],     a1 = XD[COLIDX[e + 1]];
        float a2 = XD[COLIDX[e + 2]], a3 = XD[COLIDX[e + 3]];
        t += (a0 + a1) + (a2 + a3);
    }
    for (; e < end; ++e) t += XD[COLIDX[e]];
    TSUM[i] = t * DINV[i];
}
// expand -> BUF_Z, pre-rounded to tf32 (GEMM2 A input)
__global__ void k_expand(const float4* __restrict__ W1, const float4* __restrict__ b1) {
    int i = blockIdx.x * blockDim.x + threadIdx.x;
    if (i >= NN * 32) return;
    int node = i >> 5, lane = i & 31;
    float s = TSUM[node];
    float4 w = W1[lane], b = b1[lane];
    float4 r = make_float4(tf32r(fmaxf(fmaf(s, w.x, b.x), 0.f)),
                           tf32r(fmaxf(fmaf(s, w.y, b.y), 0.f)),
                           tf32r(fmaxf(fmaf(s, w.z, b.z), 0.f)),
                           tf32r(fmaxf(fmaf(s, w.w, b.w), 0.f)));
    reinterpret_cast<float4*>(BUF_Z)[i] = r;
}

// ---------------- aggregation ----------------
template <bool RELU, bool ROUND>
__global__ void k_agg(const float4* __restrict__ bias) {
    int node = (blockIdx.x * blockDim.x + threadIdx.x) >> 5;
    if (node >= NN) return;
    int lane = threadIdx.x & 31;
    const float4* g = reinterpret_cast<const float4*>(BUF_G);
    float4 acc = g[node * 32 + lane];
    int e = ROWPTR[node], end = ROWPTR[node + 1];
    for (; e + 4 <= end; e += 4) {
        int s0 = COLIDX[e], s1 = COLIDX[e + 1], s2 = COLIDX[e + 2], s3 = COLIDX[e + 3];
        float4 a0 = g[s0 * 32 + lane], a1 = g[s1 * 32 + lane];
        float4 a2 = g[s2 * 32 + lane], a3 = g[s3 * 32 + lane];
        acc.x += (a0.x + a1.x) + (a2.x + a3.x);
        acc.y += (a0.y + a1.y) + (a2.y + a3.y);
        acc.z += (a0.z + a1.z) + (a2.z + a3.z);
        acc.w += (a0.w + a1.w) + (a2.w + a3.w);
    }
    for (; e < end; ++e) {
        float4 a = g[COLIDX[e] * 32 + lane];
        acc.x += a.x; acc.y += a.y; acc.z += a.z; acc.w += a.w;
    }
    float di = DINV[node];
    float4 b = bias[lane];
    float4 r = make_float4(fmaf(acc.x, di, b.x), fmaf(acc.y, di, b.y),
                           fmaf(acc.z, di, b.z), fmaf(acc.w, di, b.w));
    if (RELU) {
        r.x = fmaxf(r.x, 0.f); r.y = fmaxf(r.y, 0.f);
        r.z = fmaxf(r.z, 0.f); r.w = fmaxf(r.w, 0.f);
    }
    if (ROUND) { r.x = tf32r(r.x); r.y = tf32r(r.y); r.z = tf32r(r.z); r.w = tf32r(r.w); }
    reinterpret_cast<float4*>(BUF_Z)[node * 32 + lane] = r;
}

// ============= tf32 mma.sync GEMM: BUF_G[r,:] = DINV[r] * (BUF_Z @ W)[r,:] =============
// CTA: 64 M-rows x 128 N, 4 warps (warp tile 32x64). K=128, 16 k-steps of m16n8k8.
// A in smem stride 132 (conflict-free), W transposed Wt[n][k] stride 132 (conflict-free:
// bank = (4g + tig + const) mod 32 covers all 32 banks; 132*4 B row stride, k<=127 < 132).
#define AS_STRIDE 132
#define WT_STRIDE 132
#define SMEM_GTC ((64 * AS_STRIDE + 128 * WT_STRIDE) * 4)

__device__ __forceinline__ void mma_tf32(float c[4], uint32_t a0, uint32_t a1,
                                         uint32_t a2, uint32_t a3,
                                         uint32_t b0, uint32_t b1) {
    asm volatile(
        "mma.sync.aligned.m16n8k8.row.col.f32.tf32.tf32.f32 "
        "{%0,%1,%2,%3}, {%4,%5,%6,%7}, {%8,%9}, {%0,%1,%2,%3};"
        : "+f"(c[0]), "+f"(c[1]), "+f"(c[2]), "+f"(c[3])
        : "r"(a0), "r"(a1), "r"(a2), "r"(a3), "r"(b0), "r"(b1));
}

__global__ void __launch_bounds__(128) k_gemm_tc(const float* __restrict__ W) {
    extern __shared__ __align__(16) float dyn[];
    float* As = dyn;                       // [64][132]
    float* Wt = dyn + 64 * AS_STRIDE;      // [128][132]  (n-major, k contiguous-ish)
    int tid = threadIdx.x, wid = tid >> 5, lid = tid & 31;
    int g = lid >> 2, tig = lid & 3;
    int wm = wid >> 1, wn = wid & 1;
    int row0 = blockIdx.x * 64;

    // load A tile (64x128, already tf32-rounded)
    const float4* Z4 = reinterpret_cast<const float4*>(BUF_Z);
    #pragma unroll
    for (int i = 0; i < 16; i++) {
        int idx = i * 128 + tid;
        int rr = idx >> 5, q = idx & 31;
        int grow = row0 + rr; if (grow >= NN) grow = NN - 1;
        float4 v = Z4[(size_t)grow * 32 + q];
        float* p = &As[rr * AS_STRIDE + q * 4];
        p[0] = v.x; p[1] = v.y; p[2] = v.z; p[3] = v.w;
    }
    // load W (128x128), transpose + tf32-round into Wt[n][k]
    const float4* W4 = reinterpret_cast<const float4*>(W);
    #pragma unroll
    for (int i = 0; i < 32; i++) {
        int idx = i * 128 + tid;
        int kr = idx >> 5, q = idx & 31;
        float4 v = W4[kr * 32 + q];
        Wt[(q * 4 + 0) * WT_STRIDE + kr] = tf32r(v.x);
        Wt[(q * 4 + 1) * WT_STRIDE + kr] = tf32r(v.y);
        Wt[(q * 4 + 2) * WT_STRIDE + kr] = tf32r(v.z);
        Wt[(q * 4 + 3) * WT_STRIDE + kr] = tf32r(v.w);
    }
    __syncthreads();

    const uint32_t* Au = reinterpret_cast<const uint32_t*>(As);
    const uint32_t* Wu = reinterpret_cast<const uint32_t*>(Wt);
    float c[2][8][4] = {};

    #pragma unroll
    for (int ks = 0; ks < 16; ks++) {
        int k0 = ks * 8;
        uint32_t a[2][4];
        #pragma unroll
        for (int mi = 0; mi < 2; mi++) {
            int rb = wm * 32 + mi * 16 + g;
            a[mi][0] = Au[rb * AS_STRIDE + k0 + tig];
            a[mi][1] = Au[(rb + 8) * AS_STRIDE + k0 + tig];
            a[mi][2] = Au[rb * AS_STRIDE + k0 + tig + 4];
            a[mi][3] = Au[(rb + 8) * AS_STRIDE + k0 + tig + 4];
        }
        uint32_t b[8][2];
        #pragma unroll
        for (int ni = 0; ni < 8; ni++) {
            int n = wn * 64 + ni * 8 + g;
            b[ni][0] = Wu[n * WT_STRIDE + k0 + tig];
            b[ni][1] = Wu[n * WT_STRIDE + k0 + tig + 4];
        }
        #pragma unroll
        for (int mi = 0; mi < 2; mi++)
            #pragma unroll
            for (int ni = 0; ni < 8; ni++)
                mma_tf32(c[mi][ni], a[mi][0], a[mi][1], a[mi][2], a[mi][3],
                         b[ni][0], b[ni][1]);
    }

    // epilogue: scale by DINV, write BUF_G
    #pragma unroll
    for (int mi = 0; mi < 2; mi++) {
        int r0 = row0 + wm * 32 + mi * 16 + g;
        int r1 = r0 + 8;
        float s0 = (r0 < NN) ? DINV[r0] : 0.f;
        float s1 = (r1 < NN) ? DINV[r1] : 0.f;
        #pragma unroll
        for (int ni = 0; ni < 8; ni++) {
            int col = wn * 64 + ni * 8 + 2 * tig;
            if (r0 < NN)
                *reinterpret_cast<float2*>(BUF_G + (size_t)r0 * 128 + col) =
                    make_float2(c[mi][ni][0] * s0, c[mi][ni][1] * s0);
            if (r1 < NN)
                *reinterpret_cast<float2*>(BUF_G + (size_t)r1 * 128 + col) =
                    make_float2(c[mi][ni][2] * s1, c[mi][ni][3] * s1);
        }
    }
}

// ---------------- fp32 SGEMM head (COUT=64): out = BUF_Z @ Wo + bo ----------------
template <int COUT>
__global__ void __launch_bounds__(16 * (COUT / 8))
k_gemm(const float* __restrict__ W, const float* __restrict__ bias, float* __restrict__ outp) {
    constexpr int BM = 64, BK = 64, TM = 4, TN = 8;
    constexpr int TX = COUT / TN;
    constexpr int NT = TX * 16;
    constexpr int WPAD = COUT + 8;
    __shared__ __align__(16) float As[BM][BK];
    __shared__ __align__(16) float Ws[BK][WPAD];

    int tx = threadIdx.x, ty = threadIdx.y;
    int tid = ty * TX + tx;
    int row0 = blockIdx.x * BM;
    unsigned long long acc[TM][TN / 2] = {};
    const float4* A4 = reinterpret_cast<const float4*>(BUF_Z);

    for (int kb = 0; kb < HH; kb += BK) {
        for (int t = tid; t < BM * BK / 4; t += NT) {
            int r = t >> 4, kk = t & 15;
            int grow = row0 + r;
            float4 v = make_float4(0.f, 0.f, 0.f, 0.f);
            if (grow < NN) v = A4[grow * 32 + (kb >> 2) + kk];
            reinterpret_cast<float4*>(&As[r][0])[kk] = v;
        }
        for (int t = tid; t < BK * COUT / 4; t += NT) {
            int r = t / (COUT / 4), cc = t % (COUT / 4);
            reinterpret_cast<float4*>(&Ws[r][0])[cc] =
                reinterpret_cast<const float4*>(W)[(kb + r) * (COUT / 4) + cc];
        }
        __syncthreads();
        #pragma unroll 8
        for (int k = 0; k < BK; k++) {
            const unsigned long long* wr =
                reinterpret_cast<const unsigned long long*>(&Ws[k][0]);
            unsigned long long bp0 = wr[tx * 4 + 0];
            unsigned long long bp1 = wr[tx * 4 + 1];
            unsigned long long bp2 = wr[tx * 4 + 2];
            unsigned long long bp3 = wr[tx * 4 + 3];
            #pragma unroll
            for (int i = 0; i < TM; i++) {
                unsigned long long pa = pack2(As[ty * TM + i][k]);
                acc[i][0] = ffma2(pa, bp0, acc[i][0]);
                acc[i][1] = ffma2(pa, bp1, acc[i][1]);
                acc[i][2] = ffma2(pa, bp2, acc[i][2]);
                acc[i][3] = ffma2(pa, bp3, acc[i][3]);
            }
        }
        __syncthreads();
    }

    #pragma unroll
    for (int i = 0; i < TM; i++) {
        int r = row0 + ty * TM + i;
        if (r >= NN) continue;
        float2 p0 = unpack2(acc[i][0]), p1 = unpack2(acc[i][1]);
        float2 p2 = unpack2(acc[i][2]), p3 = unpack2(acc[i][3]);
        float4 bb0 = reinterpret_cast<const float4*>(bias)[tx * 2];
        float4 bb1 = reinterpret_cast<const float4*>(bias)[tx * 2 + 1];
        float4 v0 = make_float4(p0.x + bb0.x, p0.y + bb0.y, p1.x + bb0.z, p1.y + bb0.w);
        float4 v1 = make_float4(p2.x + bb1.x, p2.y + bb1.y, p3.x + bb1.z, p3.y + bb1.w);
        reinterpret_cast<float4*>(outp)[r * (COUT / 4) + tx * 2]     = v0;
        reinterpret_cast<float4*>(outp)[r * (COUT / 4) + tx * 2 + 1] = v1;
    }
}

// ---------------- launch ----------------
extern "C" void kernel_launch(void* const* d_in, const int* in_sizes, int n_in,
                              void* d_out, int out_size) {
    const float* x  = (const float*)d_in[0];
    const int*   ei = (const int*)d_in[1];
    const int*   src = ei;
    const int*   dst = ei + EE;
    const float* W1 = (const float*)d_in[2];
    const float* b1 = (const float*)d_in[3];
    const float* W2 = (const float*)d_in[4];
    const float* b2 = (const float*)d_in[5];
    const float* W3 = (const float*)d_in[6];
    const float* b3 = (const float*)d_in[7];
    const float* Wo = (const float*)d_in[8];
    const float* bo = (const float*)d_in[9];
    float* out = (float*)d_out;

    cudaFuncSetAttribute(k_gemm_tc, cudaFuncAttributeMaxDynamicSharedMemorySize, SMEM_GTC);

    // CSR build
    k_zero   <<<(NN + 255) / 256, 256>>>();
    k_hist   <<<(EE + 255) / 256, 256>>>(dst);
    k_scan1  <<<(NN + 511) / 512, 512>>>(x);
    k_scan2  <<<1, 256>>>();
    k_scan3  <<<(NN + 255) / 256, 256>>>();
    k_scatter<<<(EE + 255) / 256, 256>>>(src, dst);

    // layer 1 (rank-1 factorized)
    k_scalar_agg<<<(NN + 255) / 256, 256>>>();
    k_expand<<<(NN * 32 + 255) / 256, 256>>>((const float4*)W1, (const float4*)b1);

    // layer 2: tf32 mma.sync GEMM + agg (round for next tf32 GEMM)
    k_gemm_tc<<<(NN + 63) / 64, 128, SMEM_GTC>>>(W2);
    k_agg<true, true><<<(NN + 7) / 8, 256>>>((const float4*)b2);

    // layer 3: tf32 mma.sync GEMM + agg (no relu, no round — head is fp32)
    k_gemm_tc<<<(NN + 63) / 64, 128, SMEM_GTC>>>(W3);
    k_agg<false, false><<<(NN + 7) / 8, 256>>>((const float4*)b3);

    // linear head (fp32 FFMA2)
    k_gemm<64><<<(NN + 63) / 64, dim3(8, 16)>>>(Wo, bo, out);
}

// round 6
// speedup vs baseline: 1.4285x; 1.1248x over previous
#include <cuda_runtime.h>
#include <cstdint>

#define NN 100000
#define EE 1600000
#define HH 128

// ---------------- scratch (static device globals; no runtime alloc) ----------------
__device__ int   DEG[NN];
__device__ int   CURSOR[NN];
__device__ int   ROWPTR[NN + 1];
__device__ int   COLIDX[EE];
__device__ float DINV[NN];
__device__ float XD[NN];
__device__ float TSUM[NN];
__device__ float BUF_G[(size_t)NN * HH];
__device__ float BUF_Z[(size_t)NN * HH];
__device__ int   BLKSUM[256];
__device__ int   BLKOFF[256];
__device__ int   SCAN_CTR;

// ---------------- helpers ----------------
__device__ __forceinline__ float tf32r(float x) {   // round-to-nearest tf32 (zero-mean err)
    float r;
    asm("cvt.rna.tf32.f32 %0, %1;" : "=f"(r) : "f"(x));
    return r;
}

// ---------------- CSR build ----------------
__global__ void k_zero() {
    int i = blockIdx.x * blockDim.x + threadIdx.x;
    if (i < NN) { DEG[i] = 0; CURSOR[i] = 0; }
    if (i == 0) SCAN_CTR = 0;
}
__global__ void k_hist(const int* __restrict__ dst) {
    int e = blockIdx.x * blockDim.x + threadIdx.x;
    if (e < EE) atomicAdd(&DEG[dst[e]], 1);
}
// block-local scan + DINV/XD; last block scans BLKSUM -> BLKOFF (fused scan1+scan2)
__global__ void k_scan12(const float* __restrict__ x) {
    __shared__ int s[512];
    __shared__ int is_last;
    int i = blockIdx.x * 512 + threadIdx.x;
    int v = (i < NN) ? DEG[i] : 0;
    s[threadIdx.x] = v;
    __syncthreads();
    for (int off = 1; off < 512; off <<= 1) {
        int t = 0;
        if (threadIdx.x >= off) t = s[threadIdx.x - off];
        __syncthreads();
        if (threadIdx.x >= off) s[threadIdx.x] += t;
        __syncthreads();
    }
    if (i < NN) {
        ROWPTR[i] = s[threadIdx.x] - v;
        float di = rsqrtf((float)(v + 1));
        DINV[i] = di;
        XD[i] = x[i] * di;
    }
    if (threadIdx.x == 511) BLKSUM[blockIdx.x] = s[511];
    // last block to finish performs the block-sum scan
    __threadfence();
    if (threadIdx.x == 0)
        is_last = (atomicAdd(&SCAN_CTR, 1) == gridDim.x - 1);
    __syncthreads();
    if (is_last && threadIdx.x < 256) {
        const int NB = (NN + 511) / 512;
        int bv = (threadIdx.x < NB) ? BLKSUM[threadIdx.x] : 0;
        s[threadIdx.x] = bv;
        __syncthreads();
        for (int off = 1; off < 256; off <<= 1) {
            int t = 0;
            if (threadIdx.x >= off) t = s[threadIdx.x - off];
            __syncthreads();
            if (threadIdx.x >= off) s[threadIdx.x] += t;
            __syncthreads();
        }
        BLKOFF[threadIdx.x] = s[threadIdx.x] - bv;
    }
}
__global__ void k_scan3() {
    int i = blockIdx.x * blockDim.x + threadIdx.x;
    if (i < NN) ROWPTR[i] += BLKOFF[i >> 9];
    if (i == 0) ROWPTR[NN] = EE;
}
__global__ void k_scatter(const int* __restrict__ src, const int* __restrict__ dst) {
    int e = blockIdx.x * blockDim.x + threadIdx.x;
    if (e >= EE) return;
    int d = dst[e];
    int p = ROWPTR[d] + atomicAdd(&CURSOR[d], 1);
    COLIDX[p] = src[e];
}

// ---------------- layer-1 rank-1 path ----------------
__global__ void k_scalar_agg() {
    int i = blockIdx.x * blockDim.x + threadIdx.x;
    if (i >= NN) return;
    float t = XD[i];
    int e = ROWPTR[i], end = ROWPTR[i + 1];
    for (; e + 4 <= end; e += 4) {
        float a0 = XD[COLIDX[e]],     a1 = XD[COLIDX[e + 1]];
        float a2 = XD[COLIDX[e + 2]], a3 = XD[COLIDX[e + 3]];
        t += (a0 + a1) + (a2 + a3);
    }
    for (; e < end; ++e) t += XD[COLIDX[e]];
    TSUM[i] = t * DINV[i];
}
// expand -> BUF_Z, pre-rounded to tf32 (GEMM2 A input)
__global__ void k_expand(const float4* __restrict__ W1, const float4* __restrict__ b1) {
    int i = blockIdx.x * blockDim.x + threadIdx.x;
    if (i >= NN * 32) return;
    int node = i >> 5, lane = i & 31;
    float s = TSUM[node];
    float4 w = W1[lane], b = b1[lane];
    float4 r = make_float4(tf32r(fmaxf(fmaf(s, w.x, b.x), 0.f)),
                           tf32r(fmaxf(fmaf(s, w.y, b.y), 0.f)),
                           tf32r(fmaxf(fmaf(s, w.z, b.z), 0.f)),
                           tf32r(fmaxf(fmaf(s, w.w, b.w), 0.f)));
    reinterpret_cast<float4*>(BUF_Z)[i] = r;
}

// ---------------- aggregation ----------------
template <bool RELU>
__global__ void k_agg(const float4* __restrict__ bias) {
    int node = (blockIdx.x * blockDim.x + threadIdx.x) >> 5;
    if (node >= NN) return;
    int lane = threadIdx.x & 31;
    const float4* g = reinterpret_cast<const float4*>(BUF_G);
    float4 acc = g[node * 32 + lane];
    int e = ROWPTR[node], end = ROWPTR[node + 1];
    for (; e + 4 <= end; e += 4) {
        int s0 = COLIDX[e], s1 = COLIDX[e + 1], s2 = COLIDX[e + 2], s3 = COLIDX[e + 3];
        float4 a0 = g[s0 * 32 + lane], a1 = g[s1 * 32 + lane];
        float4 a2 = g[s2 * 32 + lane], a3 = g[s3 * 32 + lane];
        acc.x += (a0.x + a1.x) + (a2.x + a3.x);
        acc.y += (a0.y + a1.y) + (a2.y + a3.y);
        acc.z += (a0.z + a1.z) + (a2.z + a3.z);
        acc.w += (a0.w + a1.w) + (a2.w + a3.w);
    }
    for (; e < end; ++e) {
        float4 a = g[COLIDX[e] * 32 + lane];
        acc.x += a.x; acc.y += a.y; acc.z += a.z; acc.w += a.w;
    }
    float di = DINV[node];
    float4 b = bias[lane];
    float4 r = make_float4(fmaf(acc.x, di, b.x), fmaf(acc.y, di, b.y),
                           fmaf(acc.z, di, b.z), fmaf(acc.w, di, b.w));
    if (RELU) {
        r.x = fmaxf(r.x, 0.f); r.y = fmaxf(r.y, 0.f);
        r.z = fmaxf(r.z, 0.f); r.w = fmaxf(r.w, 0.f);
    }
    // always round: output feeds a tf32 mma GEMM (layer 2->3 and layer 3->head)
    r.x = tf32r(r.x); r.y = tf32r(r.y); r.z = tf32r(r.z); r.w = tf32r(r.w);
    reinterpret_cast<float4*>(BUF_Z)[node * 32 + lane] = r;
}

// ============= tf32 mma.sync GEMM: BUF_G[r,:] = DINV[r] * (BUF_Z @ W)[r,:] =============
// CTA: 64 M-rows x 128 N, 4 warps (warp tile 32x64). K=128, 16 k-steps of m16n8k8.
#define AS_STRIDE 132
#define WT_STRIDE 132
#define SMEM_GTC ((64 * AS_STRIDE + 128 * WT_STRIDE) * 4)
#define SMEM_GTO ((64 * AS_STRIDE + 64 * WT_STRIDE) * 4)

__device__ __forceinline__ void mma_tf32(float c[4], uint32_t a0, uint32_t a1,
                                         uint32_t a2, uint32_t a3,
                                         uint32_t b0, uint32_t b1) {
    asm volatile(
        "mma.sync.aligned.m16n8k8.row.col.f32.tf32.tf32.f32 "
        "{%0,%1,%2,%3}, {%4,%5,%6,%7}, {%8,%9}, {%0,%1,%2,%3};"
        : "+f"(c[0]), "+f"(c[1]), "+f"(c[2]), "+f"(c[3])
        : "r"(a0), "r"(a1), "r"(a2), "r"(a3), "r"(b0), "r"(b1));
}

__global__ void __launch_bounds__(128) k_gemm_tc(const float* __restrict__ W) {
    extern __shared__ __align__(16) float dyn[];
    float* As = dyn;                       // [64][132]
    float* Wt = dyn + 64 * AS_STRIDE;      // [128][132]
    int tid = threadIdx.x, wid = tid >> 5, lid = tid & 31;
    int g = lid >> 2, tig = lid & 3;
    int wm = wid >> 1, wn = wid & 1;
    int row0 = blockIdx.x * 64;

    const float4* Z4 = reinterpret_cast<const float4*>(BUF_Z);
    #pragma unroll
    for (int i = 0; i < 16; i++) {
        int idx = i * 128 + tid;
        int rr = idx >> 5, q = idx & 31;
        int grow = row0 + rr; if (grow >= NN) grow = NN - 1;
        float4 v = Z4[(size_t)grow * 32 + q];
        float* p = &As[rr * AS_STRIDE + q * 4];
        p[0] = v.x; p[1] = v.y; p[2] = v.z; p[3] = v.w;
    }
    const float4* W4 = reinterpret_cast<const float4*>(W);
    #pragma unroll
    for (int i = 0; i < 32; i++) {
        int idx = i * 128 + tid;
        int kr = idx >> 5, q = idx & 31;
        float4 v = W4[kr * 32 + q];
        Wt[(q * 4 + 0) * WT_STRIDE + kr] = tf32r(v.x);
        Wt[(q * 4 + 1) * WT_STRIDE + kr] = tf32r(v.y);
        Wt[(q * 4 + 2) * WT_STRIDE + kr] = tf32r(v.z);
        Wt[(q * 4 + 3) * WT_STRIDE + kr] = tf32r(v.w);
    }
    __syncthreads();

    const uint32_t* Au = reinterpret_cast<const uint32_t*>(As);
    const uint32_t* Wu = reinterpret_cast<const uint32_t*>(Wt);
    float c[2][8][4] = {};

    #pragma unroll
    for (int ks = 0; ks < 16; ks++) {
        int k0 = ks * 8;
        uint32_t a[2][4];
        #pragma unroll
        for (int mi = 0; mi < 2; mi++) {
            int rb = wm * 32 + mi * 16 + g;
            a[mi][0] = Au[rb * AS_STRIDE + k0 + tig];
            a[mi][1] = Au[(rb + 8) * AS_STRIDE + k0 + tig];
            a[mi][2] = Au[rb * AS_STRIDE + k0 + tig + 4];
            a[mi][3] = Au[(rb + 8) * AS_STRIDE + k0 + tig + 4];
        }
        uint32_t b[8][2];
        #pragma unroll
        for (int ni = 0; ni < 8; ni++) {
            int n = wn * 64 + ni * 8 + g;
            b[ni][0] = Wu[n * WT_STRIDE + k0 + tig];
            b[ni][1] = Wu[n * WT_STRIDE + k0 + tig + 4];
        }
        #pragma unroll
        for (int mi = 0; mi < 2; mi++)
            #pragma unroll
            for (int ni = 0; ni < 8; ni++)
                mma_tf32(c[mi][ni], a[mi][0], a[mi][1], a[mi][2], a[mi][3],
                         b[ni][0], b[ni][1]);
    }

    #pragma unroll
    for (int mi = 0; mi < 2; mi++) {
        int r0 = row0 + wm * 32 + mi * 16 + g;
        int r1 = r0 + 8;
        float s0 = (r0 < NN) ? DINV[r0] : 0.f;
        float s1 = (r1 < NN) ? DINV[r1] : 0.f;
        #pragma unroll
        for (int ni = 0; ni < 8; ni++) {
            int col = wn * 64 + ni * 8 + 2 * tig;
            if (r0 < NN)
                *reinterpret_cast<float2*>(BUF_G + (size_t)r0 * 128 + col) =
                    make_float2(c[mi][ni][0] * s0, c[mi][ni][1] * s0);
            if (r1 < NN)
                *reinterpret_cast<float2*>(BUF_G + (size_t)r1 * 128 + col) =
                    make_float2(c[mi][ni][2] * s1, c[mi][ni][3] * s1);
        }
    }
}

// ====== tf32 mma.sync head GEMM: out[r,:] = (BUF_Z @ Wo)[r,:] + bo   (COUT=64) ======
// CTA: 64 M-rows x 64 N, 4 warps (warp tile 32x32). K=128, 16 k-steps of m16n8k8.
__global__ void __launch_bounds__(128) k_gemm_tc_out(const float* __restrict__ W,
                                                     const float* __restrict__ bias,
                                                     float* __restrict__ outp) {
    extern __shared__ __align__(16) float dyn[];
    float* As = dyn;                       // [64][132]
    float* Wt = dyn + 64 * AS_STRIDE;      // [64][132]
    int tid = threadIdx.x, wid = tid >> 5, lid = tid & 31;
    int g = lid >> 2, tig = lid & 3;
    int wm = wid >> 1, wn = wid & 1;
    int row0 = blockIdx.x * 64;

    const float4* Z4 = reinterpret_cast<const float4*>(BUF_Z);
    #pragma unroll
    for (int i = 0; i < 16; i++) {
        int idx = i * 128 + tid;
        int rr = idx >> 5, q = idx & 31;
        int grow = row0 + rr; if (grow >= NN) grow = NN - 1;
        float4 v = Z4[(size_t)grow * 32 + q];
        float* p = &As[rr * AS_STRIDE + q * 4];
        p[0] = v.x; p[1] = v.y; p[2] = v.z; p[3] = v.w;
    }
    // W: [128][64] K-major -> Wt[n][k], tf32-rounded
    const float4* W4 = reinterpret_cast<const float4*>(W);
    #pragma unroll
    for (int i = 0; i < 16; i++) {
        int idx = i * 128 + tid;
        int kr = idx >> 4, q = idx & 15;
        float4 v = W4[kr * 16 + q];
        Wt[(q * 4 + 0) * WT_STRIDE + kr] = tf32r(v.x);
        Wt[(q * 4 + 1) * WT_STRIDE + kr] = tf32r(v.y);
        Wt[(q * 4 + 2) * WT_STRIDE + kr] = tf32r(v.z);
        Wt[(q * 4 + 3) * WT_STRIDE + kr] = tf32r(v.w);
    }
    __syncthreads();

    const uint32_t* Au = reinterpret_cast<const uint32_t*>(As);
    const uint32_t* Wu = reinterpret_cast<const uint32_t*>(Wt);
    float c[2][4][4] = {};

    #pragma unroll
    for (int ks = 0; ks < 16; ks++) {
        int k0 = ks * 8;
        uint32_t a[2][4];
        #pragma unroll
        for (int mi = 0; mi < 2; mi++) {
            int rb = wm * 32 + mi * 16 + g;
            a[mi][0] = Au[rb * AS_STRIDE + k0 + tig];
            a[mi][1] = Au[(rb + 8) * AS_STRIDE + k0 + tig];
            a[mi][2] = Au[rb * AS_STRIDE + k0 + tig + 4];
            a[mi][3] = Au[(rb + 8) * AS_STRIDE + k0 + tig + 4];
        }
        uint32_t b[4][2];
        #pragma unroll
        for (int ni = 0; ni < 4; ni++) {
            int n = wn * 32 + ni * 8 + g;
            b[ni][0] = Wu[n * WT_STRIDE + k0 + tig];
            b[ni][1] = Wu[n * WT_STRIDE + k0 + tig + 4];
        }
        #pragma unroll
        for (int mi = 0; mi < 2; mi++)
            #pragma unroll
            for (int ni = 0; ni < 4; ni++)
                mma_tf32(c[mi][ni], a[mi][0], a[mi][1], a[mi][2], a[mi][3],
                         b[ni][0], b[ni][1]);
    }

    #pragma unroll
    for (int mi = 0; mi < 2; mi++) {
        int r0 = row0 + wm * 32 + mi * 16 + g;
        int r1 = r0 + 8;
        #pragma unroll
        for (int ni = 0; ni < 4; ni++) {
            int col = wn * 32 + ni * 8 + 2 * tig;
            float2 bb = *reinterpret_cast<const float2*>(bias + col);
            if (r0 < NN)
                *reinterpret_cast<float2*>(outp + (size_t)r0 * 64 + col) =
                    make_float2(c[mi][ni][0] + bb.x, c[mi][ni][1] + bb.y);
            if (r1 < NN)
                *reinterpret_cast<float2*>(outp + (size_t)r1 * 64 + col) =
                    make_float2(c[mi][ni][2] + bb.x, c[mi][ni][3] + bb.y);
        }
    }
}

// ---------------- launch ----------------
extern "C" void kernel_launch(void* const* d_in, const int* in_sizes, int n_in,
                              void* d_out, int out_size) {
    const float* x  = (const float*)d_in[0];
    const int*   ei = (const int*)d_in[1];
    const int*   src = ei;
    const int*   dst = ei + EE;
    const float* W1 = (const float*)d_in[2];
    const float* b1 = (const float*)d_in[3];
    const float* W2 = (const float*)d_in[4];
    const float* b2 = (const float*)d_in[5];
    const float* W3 = (const float*)d_in[6];
    const float* b3 = (const float*)d_in[7];
    const float* Wo = (const float*)d_in[8];
    const float* bo = (const float*)d_in[9];
    float* out = (float*)d_out;

    cudaFuncSetAttribute(k_gemm_tc, cudaFuncAttributeMaxDynamicSharedMemorySize, SMEM_GTC);
    cudaFuncSetAttribute(k_gemm_tc_out, cudaFuncAttributeMaxDynamicSharedMemorySize, SMEM_GTO);

    // CSR build
    k_zero   <<<(NN + 255) / 256, 256>>>();
    k_hist   <<<(EE + 255) / 256, 256>>>(dst);
    k_scan12 <<<(NN + 511) / 512, 512>>>(x);
    k_scan3  <<<(NN + 255) / 256, 256>>>();
    k_scatter<<<(EE + 255) / 256, 256>>>(src, dst);

    // layer 1 (rank-1 factorized)
    k_scalar_agg<<<(NN + 255) / 256, 256>>>();
    k_expand<<<(NN * 32 + 255) / 256, 256>>>((const float4*)W1, (const float4*)b1);

    // layer 2: tf32 mma GEMM + agg
    k_gemm_tc<<<(NN + 63) / 64, 128, SMEM_GTC>>>(W2);
    k_agg<true><<<(NN + 7) / 8, 256>>>((const float4*)b2);

    // layer 3: tf32 mma GEMM + agg (no relu)
    k_gemm_tc<<<(NN + 63) / 64, 128, SMEM_GTC>>>(W3);
    k_agg<false><<<(NN + 7) / 8, 256>>>((const float4*)b3);

    // linear head (tf32 mma)
    k_gemm_tc_out<<<(NN + 63) / 64, 128, SMEM_GTO>>>(Wo, bo, out);
}

// round 7
// speedup vs baseline: 1.6098x; 1.1269x over previous
#include <cuda_runtime.h>
#include <cuda_fp16.h>
#include <cstdint>

#define NN 100000
#define EE 1600000
#define HH 128

// ---------------- scratch (static device globals; no runtime alloc) ----------------
__device__ int     DEG[NN];
__device__ int     CURSOR[NN];
__device__ int     ROWPTR[NN + 1];
__device__ int     COLIDX[EE];
__device__ float   DINV[NN];
__device__ float   XD[NN];
__device__ float   TSUM[NN];
__device__ __half2 BUF_GH[(size_t)NN * (HH / 2)];   // fp16 messages g = h * dinv
__device__ float   BUF_Z[(size_t)NN * HH];
__device__ int     BLKSUM[256];
__device__ int     BLKOFF[256];
__device__ int     SCAN_CTR;

// ---------------- helpers ----------------
__device__ __forceinline__ float tf32r(float x) {   // round-to-nearest tf32 (zero-mean err)
    float r;
    asm("cvt.rna.tf32.f32 %0, %1;" : "=f"(r) : "f"(x));
    return r;
}

// ---------------- CSR build ----------------
__global__ void k_zero() {
    int i = blockIdx.x * blockDim.x + threadIdx.x;
    if (i < NN) { DEG[i] = 0; CURSOR[i] = 0; }
    if (i == 0) SCAN_CTR = 0;
}
__global__ void k_hist(const int* __restrict__ dst) {
    int e = blockIdx.x * blockDim.x + threadIdx.x;
    if (e < EE) atomicAdd(&DEG[dst[e]], 1);
}
// block-local scan + DINV/XD; last block scans BLKSUM -> BLKOFF (fused scan1+scan2)
__global__ void k_scan12(const float* __restrict__ x) {
    __shared__ int s[512];
    __shared__ int is_last;
    int i = blockIdx.x * 512 + threadIdx.x;
    int v = (i < NN) ? DEG[i] : 0;
    s[threadIdx.x] = v;
    __syncthreads();
    for (int off = 1; off < 512; off <<= 1) {
        int t = 0;
        if (threadIdx.x >= off) t = s[threadIdx.x - off];
        __syncthreads();
        if (threadIdx.x >= off) s[threadIdx.x] += t;
        __syncthreads();
    }
    if (i < NN) {
        ROWPTR[i] = s[threadIdx.x] - v;
        float di = rsqrtf((float)(v + 1));
        DINV[i] = di;
        XD[i] = x[i] * di;
    }
    if (threadIdx.x == 511) BLKSUM[blockIdx.x] = s[511];
    __threadfence();
    if (threadIdx.x == 0)
        is_last = (atomicAdd(&SCAN_CTR, 1) == gridDim.x - 1);
    __syncthreads();
    if (is_last && threadIdx.x < 256) {
        const int NB = (NN + 511) / 512;
        int bv = (threadIdx.x < NB) ? BLKSUM[threadIdx.x] : 0;
        s[threadIdx.x] = bv;
        __syncthreads();
        for (int off = 1; off < 256; off <<= 1) {
            int t = 0;
            if (threadIdx.x >= off) t = s[threadIdx.x - off];
            __syncthreads();
            if (threadIdx.x >= off) s[threadIdx.x] += t;
            __syncthreads();
        }
        BLKOFF[threadIdx.x] = s[threadIdx.x] - bv;
    }
}
__global__ void k_scan3() {
    int i = blockIdx.x * blockDim.x + threadIdx.x;
    if (i < NN) ROWPTR[i] += BLKOFF[i >> 9];
    if (i == 0) ROWPTR[NN] = EE;
}
__global__ void k_scatter(const int* __restrict__ src, const int* __restrict__ dst) {
    int e = blockIdx.x * blockDim.x + threadIdx.x;
    if (e >= EE) return;
    int d = dst[e];
    int p = ROWPTR[d] + atomicAdd(&CURSOR[d], 1);
    COLIDX[p] = src[e];
}

// ---------------- layer-1 rank-1 path ----------------
__global__ void k_scalar_agg() {
    int i = blockIdx.x * blockDim.x + threadIdx.x;
    if (i >= NN) return;
    float t = XD[i];
    int e = ROWPTR[i], end = ROWPTR[i + 1];
    for (; e + 4 <= end; e += 4) {
        float a0 = XD[COLIDX[e]],     a1 = XD[COLIDX[e + 1]];
        float a2 = XD[COLIDX[e + 2]], a3 = XD[COLIDX[e + 3]];
        t += (a0 + a1) + (a2 + a3);
    }
    for (; e < end; ++e) t += XD[COLIDX[e]];
    TSUM[i] = t * DINV[i];
}
// expand -> BUF_Z, pre-rounded to tf32 (GEMM2 A input)
__global__ void k_expand(const float4* __restrict__ W1, const float4* __restrict__ b1) {
    int i = blockIdx.x * blockDim.x + threadIdx.x;
    if (i >= NN * 32) return;
    int node = i >> 5, lane = i & 31;
    float s = TSUM[node];
    float4 w = W1[lane], b = b1[lane];
    float4 r = make_float4(tf32r(fmaxf(fmaf(s, w.x, b.x), 0.f)),
                           tf32r(fmaxf(fmaf(s, w.y, b.y), 0.f)),
                           tf32r(fmaxf(fmaf(s, w.z, b.z), 0.f)),
                           tf32r(fmaxf(fmaf(s, w.w, b.w), 0.f)));
    reinterpret_cast<float4*>(BUF_Z)[i] = r;
}

// ---------------- aggregation (fp16 messages, fp32 accumulate) ----------------
__device__ __forceinline__ void acc_gh(float4& acc, uint2 u) {
    float2 f0 = __half22float2(*reinterpret_cast<__half2*>(&u.x));
    float2 f1 = __half22float2(*reinterpret_cast<__half2*>(&u.y));
    acc.x += f0.x; acc.y += f0.y; acc.z += f1.x; acc.w += f1.y;
}

template <bool RELU>
__global__ void k_agg(const float4* __restrict__ bias) {
    int node = (blockIdx.x * blockDim.x + threadIdx.x) >> 5;
    if (node >= NN) return;
    int lane = threadIdx.x & 31;
    const uint2* g = reinterpret_cast<const uint2*>(BUF_GH);
    float4 acc = make_float4(0.f, 0.f, 0.f, 0.f);
    acc_gh(acc, g[node * 32 + lane]);                 // self-loop term
    int e = ROWPTR[node], end = ROWPTR[node + 1];
    for (; e + 4 <= end; e += 4) {
        int s0 = COLIDX[e], s1 = COLIDX[e + 1], s2 = COLIDX[e + 2], s3 = COLIDX[e + 3];
        uint2 u0 = g[s0 * 32 + lane], u1 = g[s1 * 32 + lane];
        uint2 u2 = g[s2 * 32 + lane], u3 = g[s3 * 32 + lane];
        acc_gh(acc, u0); acc_gh(acc, u1); acc_gh(acc, u2); acc_gh(acc, u3);
    }
    for (; e < end; ++e) acc_gh(acc, g[COLIDX[e] * 32 + lane]);
    float di = DINV[node];
    float4 b = bias[lane];
    float4 r = make_float4(fmaf(acc.x, di, b.x), fmaf(acc.y, di, b.y),
                           fmaf(acc.z, di, b.z), fmaf(acc.w, di, b.w));
    if (RELU) {
        r.x = fmaxf(r.x, 0.f); r.y = fmaxf(r.y, 0.f);
        r.z = fmaxf(r.z, 0.f); r.w = fmaxf(r.w, 0.f);
    }
    // always round: output feeds a tf32 mma GEMM
    r.x = tf32r(r.x); r.y = tf32r(r.y); r.z = tf32r(r.z); r.w = tf32r(r.w);
    reinterpret_cast<float4*>(BUF_Z)[node * 32 + lane] = r;
}

// ============= tf32 mma.sync GEMM: BUF_GH[r,:] = fp16(DINV[r] * (BUF_Z @ W)[r,:]) ======
#define AS_STRIDE 132
#define WT_STRIDE 132
#define SMEM_GTC ((64 * AS_STRIDE + 128 * WT_STRIDE) * 4)
#define SMEM_GTO ((64 * AS_STRIDE + 64 * WT_STRIDE) * 4)

__device__ __forceinline__ void mma_tf32(float c[4], uint32_t a0, uint32_t a1,
                                         uint32_t a2, uint32_t a3,
                                         uint32_t b0, uint32_t b1) {
    asm volatile(
        "mma.sync.aligned.m16n8k8.row.col.f32.tf32.tf32.f32 "
        "{%0,%1,%2,%3}, {%4,%5,%6,%7}, {%8,%9}, {%0,%1,%2,%3};"
        : "+f"(c[0]), "+f"(c[1]), "+f"(c[2]), "+f"(c[3])
        : "r"(a0), "r"(a1), "r"(a2), "r"(a3), "r"(b0), "r"(b1));
}

__global__ void __launch_bounds__(128) k_gemm_tc(const float* __restrict__ W) {
    extern __shared__ __align__(16) float dyn[];
    float* As = dyn;                       // [64][132]
    float* Wt = dyn + 64 * AS_STRIDE;      // [128][132]
    int tid = threadIdx.x, wid = tid >> 5, lid = tid & 31;
    int g = lid >> 2, tig = lid & 3;
    int wm = wid >> 1, wn = wid & 1;
    int row0 = blockIdx.x * 64;

    const float4* Z4 = reinterpret_cast<const float4*>(BUF_Z);
    #pragma unroll
    for (int i = 0; i < 16; i++) {
        int idx = i * 128 + tid;
        int rr = idx >> 5, q = idx & 31;
        int grow = row0 + rr; if (grow >= NN) grow = NN - 1;
        float4 v = Z4[(size_t)grow * 32 + q];
        float* p = &As[rr * AS_STRIDE + q * 4];
        p[0] = v.x; p[1] = v.y; p[2] = v.z; p[3] = v.w;
    }
    const float4* W4 = reinterpret_cast<const float4*>(W);
    #pragma unroll
    for (int i = 0; i < 32; i++) {
        int idx = i * 128 + tid;
        int kr = idx >> 5, q = idx & 31;
        float4 v = W4[kr * 32 + q];
        Wt[(q * 4 + 0) * WT_STRIDE + kr] = tf32r(v.x);
        Wt[(q * 4 + 1) * WT_STRIDE + kr] = tf32r(v.y);
        Wt[(q * 4 + 2) * WT_STRIDE + kr] = tf32r(v.z);
        Wt[(q * 4 + 3) * WT_STRIDE + kr] = tf32r(v.w);
    }
    __syncthreads();

    const uint32_t* Au = reinterpret_cast<const uint32_t*>(As);
    const uint32_t* Wu = reinterpret_cast<const uint32_t*>(Wt);
    float c[2][8][4] = {};

    #pragma unroll
    for (int ks = 0; ks < 16; ks++) {
        int k0 = ks * 8;
        uint32_t a[2][4];
        #pragma unroll
        for (int mi = 0; mi < 2; mi++) {
            int rb = wm * 32 + mi * 16 + g;
            a[mi][0] = Au[rb * AS_STRIDE + k0 + tig];
            a[mi][1] = Au[(rb + 8) * AS_STRIDE + k0 + tig];
            a[mi][2] = Au[rb * AS_STRIDE + k0 + tig + 4];
            a[mi][3] = Au[(rb + 8) * AS_STRIDE + k0 + tig + 4];
        }
        uint32_t b[8][2];
        #pragma unroll
        for (int ni = 0; ni < 8; ni++) {
            int n = wn * 64 + ni * 8 + g;
            b[ni][0] = Wu[n * WT_STRIDE + k0 + tig];
            b[ni][1] = Wu[n * WT_STRIDE + k0 + tig + 4];
        }
        #pragma unroll
        for (int mi = 0; mi < 2; mi++)
            #pragma unroll
            for (int ni = 0; ni < 8; ni++)
                mma_tf32(c[mi][ni], a[mi][0], a[mi][1], a[mi][2], a[mi][3],
                         b[ni][0], b[ni][1]);
    }

    // epilogue: scale by DINV, convert to fp16 messages
    #pragma unroll
    for (int mi = 0; mi < 2; mi++) {
        int r0 = row0 + wm * 32 + mi * 16 + g;
        int r1 = r0 + 8;
        float s0 = (r0 < NN) ? DINV[r0] : 0.f;
        float s1 = (r1 < NN) ? DINV[r1] : 0.f;
        #pragma unroll
        for (int ni = 0; ni < 8; ni++) {
            int c2 = wn * 32 + ni * 4 + tig;   // half2 column index
            if (r0 < NN)
                BUF_GH[(size_t)r0 * 64 + c2] =
                    __floats2half2_rn(c[mi][ni][0] * s0, c[mi][ni][1] * s0);
            if (r1 < NN)
                BUF_GH[(size_t)r1 * 64 + c2] =
                    __floats2half2_rn(c[mi][ni][2] * s1, c[mi][ni][3] * s1);
        }
    }
}

// ====== tf32 mma.sync head GEMM: out[r,:] = (BUF_Z @ Wo)[r,:] + bo   (COUT=64) ======
__global__ void __launch_bounds__(128) k_gemm_tc_out(const float* __restrict__ W,
                                                     const float* __restrict__ bias,
                                                     float* __restrict__ outp) {
    extern __shared__ __align__(16) float dyn[];
    float* As = dyn;                       // [64][132]
    float* Wt = dyn + 64 * AS_STRIDE;      // [64][132]
    int tid = threadIdx.x, wid = tid >> 5, lid = tid & 31;
    int g = lid >> 2, tig = lid & 3;
    int wm = wid >> 1, wn = wid & 1;
    int row0 = blockIdx.x * 64;

    const float4* Z4 = reinterpret_cast<const float4*>(BUF_Z);
    #pragma unroll
    for (int i = 0; i < 16; i++) {
        int idx = i * 128 + tid;
        int rr = idx >> 5, q = idx & 31;
        int grow = row0 + rr; if (grow >= NN) grow = NN - 1;
        float4 v = Z4[(size_t)grow * 32 + q];
        float* p = &As[rr * AS_STRIDE + q * 4];
        p[0] = v.x; p[1] = v.y; p[2] = v.z; p[3] = v.w;
    }
    const float4* W4 = reinterpret_cast<const float4*>(W);
    #pragma unroll
    for (int i = 0; i < 16; i++) {
        int idx = i * 128 + tid;
        int kr = idx >> 4, q = idx & 15;
        float4 v = W4[kr * 16 + q];
        Wt[(q * 4 + 0) * WT_STRIDE + kr] = tf32r(v.x);
        Wt[(q * 4 + 1) * WT_STRIDE + kr] = tf32r(v.y);
        Wt[(q * 4 + 2) * WT_STRIDE + kr] = tf32r(v.z);
        Wt[(q * 4 + 3) * WT_STRIDE + kr] = tf32r(v.w);
    }
    __syncthreads();

    const uint32_t* Au = reinterpret_cast<const uint32_t*>(As);
    const uint32_t* Wu = reinterpret_cast<const uint32_t*>(Wt);
    float c[2][4][4] = {};

    #pragma unroll
    for (int ks = 0; ks < 16; ks++) {
        int k0 = ks * 8;
        uint32_t a[2][4];
        #pragma unroll
        for (int mi = 0; mi < 2; mi++) {
            int rb = wm * 32 + mi * 16 + g;
            a[mi][0] = Au[rb * AS_STRIDE + k0 + tig];
            a[mi][1] = Au[(rb + 8) * AS_STRIDE + k0 + tig];
            a[mi][2] = Au[rb * AS_STRIDE + k0 + tig + 4];
            a[mi][3] = Au[(rb + 8) * AS_STRIDE + k0 + tig + 4];
        }
        uint32_t b[4][2];
        #pragma unroll
        for (int ni = 0; ni < 4; ni++) {
            int n = wn * 32 + ni * 8 + g;
            b[ni][0] = Wu[n * WT_STRIDE + k0 + tig];
            b[ni][1] = Wu[n * WT_STRIDE + k0 + tig + 4];
        }
        #pragma unroll
        for (int mi = 0; mi < 2; mi++)
            #pragma unroll
            for (int ni = 0; ni < 4; ni++)
                mma_tf32(c[mi][ni], a[mi][0], a[mi][1], a[mi][2], a[mi][3],
                         b[ni][0], b[ni][1]);
    }

    #pragma unroll
    for (int mi = 0; mi < 2; mi++) {
        int r0 = row0 + wm * 32 + mi * 16 + g;
        int r1 = r0 + 8;
        #pragma unroll
        for (int ni = 0; ni < 4; ni++) {
            int col = wn * 32 + ni * 8 + 2 * tig;
            float2 bb = *reinterpret_cast<const float2*>(bias + col);
            if (r0 < NN)
                *reinterpret_cast<float2*>(outp + (size_t)r0 * 64 + col) =
                    make_float2(c[mi][ni][0] + bb.x, c[mi][ni][1] + bb.y);
            if (r1 < NN)
                *reinterpret_cast<float2*>(outp + (size_t)r1 * 64 + col) =
                    make_float2(c[mi][ni][2] + bb.x, c[mi][ni][3] + bb.y);
        }
    }
}

// ---------------- launch ----------------
extern "C" void kernel_launch(void* const* d_in, const int* in_sizes, int n_in,
                              void* d_out, int out_size) {
    const float* x  = (const float*)d_in[0];
    const int*   ei = (const int*)d_in[1];
    const int*   src = ei;
    const int*   dst = ei + EE;
    const float* W1 = (const float*)d_in[2];
    const float* b1 = (const float*)d_in[3];
    const float* W2 = (const float*)d_in[4];
    const float* b2 = (const float*)d_in[5];
    const float* W3 = (const float*)d_in[6];
    const float* b3 = (const float*)d_in[7];
    const float* Wo = (const float*)d_in[8];
    const float* bo = (const float*)d_in[9];
    float* out = (float*)d_out;

    cudaFuncSetAttribute(k_gemm_tc, cudaFuncAttributeMaxDynamicSharedMemorySize, SMEM_GTC);
    cudaFuncSetAttribute(k_gemm_tc_out, cudaFuncAttributeMaxDynamicSharedMemorySize, SMEM_GTO);

    // CSR build
    k_zero   <<<(NN + 255) / 256, 256>>>();
    k_hist   <<<(EE + 255) / 256, 256>>>(dst);
    k_scan12 <<<(NN + 511) / 512, 512>>>(x);
    k_scan3  <<<(NN + 255) / 256, 256>>>();
    k_scatter<<<(EE + 255) / 256, 256>>>(src, dst);

    // layer 1 (rank-1 factorized)
    k_scalar_agg<<<(NN + 255) / 256, 256>>>();
    k_expand<<<(NN * 32 + 255) / 256, 256>>>((const float4*)W1, (const float4*)b1);

    // layer 2: tf32 mma GEMM (fp16 message epilogue) + agg
    k_gemm_tc<<<(NN + 63) / 64, 128, SMEM_GTC>>>(W2);
    k_agg<true><<<(NN + 7) / 8, 256>>>((const float4*)b2);

    // layer 3
    k_gemm_tc<<<(NN + 63) / 64, 128, SMEM_GTC>>>(W3);
    k_agg<false><<<(NN + 7) / 8, 256>>>((const float4*)b3);

    // linear head (tf32 mma)
    k_gemm_tc_out<<<(NN + 63) / 64, 128, SMEM_GTO>>>(Wo, bo, out);
}